// round 2
// baseline (speedup 1.0000x reference)
#include <cuda_runtime.h>
#include <cuda_bf16.h>
#include <cstdint>

// Problem dims (fixed by the reference): N=32, K=32, T=128, H=768
#define NN 32
#define KK 32
#define TT 128
#define HH 768
#define H2 1536

// Output layout: float32 concat of (score, shifted_encoded, shifted_mask, shifted_use, shifted_index)
#define OFF_SCORE 0                         // 32*32          = 1024
#define OFF_ENC   1024                      // 32*128*768     = 3145728
#define OFF_MASK  (1024 + 3145728)          // 32*128         = 4096
#define OFF_USE   (OFF_MASK + 4096)         // 32*768         = 24576
#define OFF_IDX   (OFF_USE + 24576)         // 32*128         = 4096
// total = 3179520

// Scratch (no allocations allowed)
__device__ float g_cqk[NN * HH];   // cqk_pro
__device__ float g_v[NN * HH];     // v[n,h]
__device__ float g_c[NN];          // b_k . cqk_pro[n]

// ---------------------------------------------------------------------------
// Kernel A: cqk_pro[n,g] = b_cqk[g] + sum_t cqk[n,t] * W_cqk[g,t]
//   cqk[n,:] = [contexts[n,2,:], tracked[n,:]]  (length 1536)
// One warp per (n,g). 24576 warps. Coalesced float4 loads of the W row.
// ---------------------------------------------------------------------------
__global__ void __launch_bounds__(256) kA_cqkpro(
    const float* __restrict__ ctx,      // (N,3,H)
    const float* __restrict__ tracked,  // (N,H)
    const float* __restrict__ W_cqk,    // (H, 2H) row-major
    const float* __restrict__ b_cqk)    // (H,)
{
    int wid  = blockIdx.x * 8 + (threadIdx.x >> 5);
    int lane = threadIdx.x & 31;
    int n = wid / HH;
    int g = wid - n * HH;

    const float4* W4 = reinterpret_cast<const float4*>(W_cqk + (size_t)g * H2);
    const float4* q4 = reinterpret_cast<const float4*>(ctx + ((size_t)n * 3 + 2) * HH);
    const float4* t4 = reinterpret_cast<const float4*>(tracked + (size_t)n * HH);

    float s = 0.f;
#pragma unroll
    for (int j = lane; j < 192; j += 32) {
        float4 w = W4[j];
        float4 x = q4[j];
        s = fmaf(w.x, x.x, s); s = fmaf(w.y, x.y, s);
        s = fmaf(w.z, x.z, s); s = fmaf(w.w, x.w, s);
        float4 w2 = W4[192 + j];
        float4 x2 = t4[j];
        s = fmaf(w2.x, x2.x, s); s = fmaf(w2.y, x2.y, s);
        s = fmaf(w2.z, x2.z, s); s = fmaf(w2.w, x2.w, s);
    }
#pragma unroll
    for (int o = 16; o > 0; o >>= 1) s += __shfl_down_sync(0xffffffffu, s, o);
    if (lane == 0) g_cqk[n * HH + g] = s + b_cqk[g];
}

// ---------------------------------------------------------------------------
// Kernel B: v[n,h] = sum_g W_k[g,h] * cqk_pro[n,g];  c[n] = b_k . cqk_pro[n]
// blockIdx.y = n, blockIdx.x = h-chunk of 128, 128 threads.
// W_k loads are coalesced over h; cqk_pro broadcast from smem.
// ---------------------------------------------------------------------------
__global__ void __launch_bounds__(128) kB_v(
    const float* __restrict__ W_k,   // (H,H) row-major: W_k[g*H + h]
    const float* __restrict__ b_k)   // (H,)
{
    int n   = blockIdx.y;
    int tid = threadIdx.x;
    int h   = blockIdx.x * 128 + tid;

    __shared__ float sc[HH];
    for (int i = tid; i < HH; i += 128) sc[i] = g_cqk[n * HH + i];
    __syncthreads();

    float acc = 0.f;
    const float* Wcol = W_k + h;
#pragma unroll 8
    for (int g = 0; g < HH; ++g)
        acc = fmaf(__ldg(Wcol + (size_t)g * HH), sc[g], acc);
    g_v[n * HH + h] = acc;

    if (blockIdx.x == 0) {
        __shared__ float red[128];
        float pc = 0.f;
        for (int i = tid; i < HH; i += 128) pc = fmaf(b_k[i], sc[i], pc);
        red[tid] = pc;
        __syncthreads();
#pragma unroll
        for (int o = 64; o > 0; o >>= 1) {
            if (tid < o) red[tid] += red[tid + o];
            __syncthreads();
        }
        if (tid == 0) g_c[n] = red[0];
    }
}

// ---------------------------------------------------------------------------
// Kernel C: score[n,k] = p1[n,k,:].v[n,:] + c[n], masked. Warp per (n,k).
// ck_mask is int32 (bool inputs are materialized as int32 by the harness).
// ---------------------------------------------------------------------------
__global__ void __launch_bounds__(256) kC_score(
    const float* __restrict__ p1,        // (N,K,H)
    const int* __restrict__ ck_mask,     // (N,K) bool-as-int32
    float* __restrict__ out)
{
    int wid  = blockIdx.x * 8 + (threadIdx.x >> 5);
    int lane = threadIdx.x & 31;
    int n = wid / KK;
    int k = wid - n * KK;

    const float4* p4 = reinterpret_cast<const float4*>(p1 + ((size_t)n * KK + k) * HH);
    const float4* v4 = reinterpret_cast<const float4*>(g_v + (size_t)n * HH);

    float s = 0.f;
#pragma unroll
    for (int j = lane; j < 192; j += 32) {
        float4 a = p4[j];
        float4 b = v4[j];
        s = fmaf(a.x, b.x, s); s = fmaf(a.y, b.y, s);
        s = fmaf(a.z, b.z, s); s = fmaf(a.w, b.w, s);
    }
#pragma unroll
    for (int o = 16; o > 0; o >>= 1) s += __shfl_down_sync(0xffffffffu, s, o);
    if (lane == 0) {
        s += g_c[n];
        if (ck_mask[n * KK + k] == 0) s = -1e20f;
        out[OFF_SCORE + n * KK + k] = s;
    }
}

// ---------------------------------------------------------------------------
// Kernel D: gathers (independent of A/B/C).
//   shifted_encoded: pool_encoded_0[n, label[n]]  (N,T,H) as float4 copy
//   shifted_use:     pool_encoded_1[n, label[n]]  (N,H)   as float4 copy
//   shifted_mask:    pool_mask[n, label[n]]       (N,T)   bool(int32) -> float
//   shifted_index:   pool_tokens[n, label[n]]     (N,T)   int  -> float
// ---------------------------------------------------------------------------
__global__ void __launch_bounds__(256) kD_gather(
    const float* __restrict__ p0,        // (N,K,T,H)
    const float* __restrict__ p1,        // (N,K,H)
    const int* __restrict__ pmask,       // (N,K,T) bool-as-int32
    const int* __restrict__ label,       // (N,)
    const int* __restrict__ ptok,        // (N,K,T)
    float* __restrict__ out)
{
    int idx = blockIdx.x * 256 + threadIdx.x;
    const int ENC_F4 = NN * TT * HH / 4;          // 786432
    const int USE_F4 = NN * HH / 4;               // 6144
    const int MT     = NN * TT;                   // 4096

    if (idx < ENC_F4) {
        int per_n = TT * HH / 4;                  // 24576
        int n = idx / per_n;
        int r = idx - n * per_n;
        int lab = label[n];
        const float4* src = reinterpret_cast<const float4*>(
            p0 + ((size_t)(n * KK + lab)) * TT * HH);
        float4* dst = reinterpret_cast<float4*>(out + OFF_ENC + (size_t)n * TT * HH);
        dst[r] = src[r];
        return;
    }
    idx -= ENC_F4;
    if (idx < USE_F4) {
        int per_n = HH / 4;                       // 192
        int n = idx / per_n;
        int r = idx - n * per_n;
        int lab = label[n];
        const float4* src = reinterpret_cast<const float4*>(
            p1 + ((size_t)(n * KK + lab)) * HH);
        float4* dst = reinterpret_cast<float4*>(out + OFF_USE + (size_t)n * HH);
        dst[r] = src[r];
        return;
    }
    idx -= USE_F4;
    if (idx < MT) {
        int n = idx / TT;
        int t = idx - n * TT;
        int lab = label[n];
        out[OFF_MASK + idx] = (pmask[((size_t)(n * KK + lab)) * TT + t] != 0) ? 1.0f : 0.0f;
        return;
    }
    idx -= MT;
    if (idx < MT) {
        int n = idx / TT;
        int t = idx - n * TT;
        int lab = label[n];
        out[OFF_IDX + idx] = (float)ptok[((size_t)(n * KK + lab)) * TT + t];
        return;
    }
}

extern "C" void kernel_launch(void* const* d_in, const int* in_sizes, int n_in,
                              void* d_out, int out_size) {
    const float* ctx     = (const float*)d_in[0];   // contexts_encoded_1 (N,3,H)
    const float* tracked = (const float*)d_in[1];   // tracked_knowledge_use (N,H)
    const float* p0      = (const float*)d_in[2];   // pool_encoded_0 (N,K,T,H)
    const float* p1      = (const float*)d_in[3];   // pool_encoded_1 (N,K,H)
    const int*   pmask   = (const int*)d_in[4];     // pool_mask (N,K,T) bool-as-int32
    const int*   ckmask  = (const int*)d_in[5];     // ck_mask (N,K) bool-as-int32
    const int*   label   = (const int*)d_in[6];     // label (N,)
    const int*   ptok    = (const int*)d_in[7];     // pool_tokens (N,K,T)
    const float* W_cqk   = (const float*)d_in[8];   // (H,2H)
    const float* b_cqk   = (const float*)d_in[9];   // (H,)
    const float* W_k     = (const float*)d_in[10];  // (H,H)
    const float* b_k     = (const float*)d_in[11];  // (H,)
    float* out = (float*)d_out;

    // Gather first (independent of the score chain)
    {
        int total = NN * TT * HH / 4 + NN * HH / 4 + NN * TT + NN * TT; // 800768
        kD_gather<<<(total + 255) / 256, 256>>>(p0, p1, pmask, label, ptok, out);
    }
    // cqk_pro: 32*768 warps
    kA_cqkpro<<<(NN * HH) / 8, 256>>>(ctx, tracked, W_cqk, b_cqk);
    // v + c
    {
        dim3 grid(HH / 128, NN);
        kB_v<<<grid, 128>>>(W_k, b_k);
    }
    // score: 1024 warps
    kC_score<<<(NN * KK) / 8, 256>>>(p1, ckmask, out);
}